// round 6
// baseline (speedup 1.0000x reference)
#include <cuda_runtime.h>
#include <math.h>

#define LROWS    512
#define NS       8192            // samples per row
#define NREF     8192            // reference grid points
#define NG       (3*NREF)        // 24576 circular-CDF grid points
#define NTHREADS 1024
#define IPT      (NS/NTHREADS)   // 8 items per thread
#define KPT      (NREF/NTHREADS) // 8 inversion queries per thread
#define GPT_P    (NREF/NTHREADS) // 8 grid points per thread per period

#define STEPG     (3.0f/24575.0f)

__device__ float g_rowsum[LROWS];
__device__ float g_h[(size_t)2 * LROWS * NS];   // h1 then h2, 32 MB scratch

// ---------------------------------------------------------------------------
// block-wide exclusive scans (warp shuffle + 32-entry partials)
// ---------------------------------------------------------------------------
__device__ __forceinline__ int block_excl_scan_int(int local_total, int tid, int* s_part)
{
    __syncthreads();
    int lane = tid & 31, wid = tid >> 5;
    int x = local_total;
#pragma unroll
    for (int d = 1; d < 32; d <<= 1) {
        int t = __shfl_up_sync(0xffffffffu, x, d);
        if (lane >= d) x += t;
    }
    if (lane == 31) s_part[wid] = x;
    __syncthreads();
    if (wid == 0) {
        int v = s_part[lane];
        int y = v;
#pragma unroll
        for (int d = 1; d < 32; d <<= 1) {
            int t = __shfl_up_sync(0xffffffffu, y, d);
            if (lane >= d) y += t;
        }
        s_part[lane] = y - v;                  // exclusive warp offsets
    }
    __syncthreads();
    return s_part[wid] + (x - local_total);
}

__device__ __forceinline__ float block_excl_scan_float(float local_total, int tid, float* s_part)
{
    __syncthreads();
    int lane = tid & 31, wid = tid >> 5;
    float x = local_total;
#pragma unroll
    for (int d = 1; d < 32; d <<= 1) {
        float t = __shfl_up_sync(0xffffffffu, x, d);
        if (lane >= d) x += t;
    }
    if (lane == 31) s_part[wid] = x;
    __syncthreads();
    if (wid == 0) {
        float v = s_part[lane];
        float y = v;
#pragma unroll
        for (int d = 1; d < 32; d <<= 1) {
            float t = __shfl_up_sync(0xffffffffu, y, d);
            if (lane >= d) y += t;
        }
        s_part[lane] = y - v;
    }
    __syncthreads();
    return s_part[wid] + (x - local_total);
}

// ---------------------------------------------------------------------------
// one embedding pass per block: grid = 1024 = 2 datasets x 512 rows
// ---------------------------------------------------------------------------
__global__ void __launch_bounds__(NTHREADS, 1)
lcot_emb_kernel(const float* __restrict__ x1, const float* __restrict__ w1,
                const float* __restrict__ x2, const float* __restrict__ w2)
{
    extern __shared__ char smem_raw[];
    float2* sc  = (float2*)smem_raw;           // [NS] (x, weight->cdf) pairs
    int*   offs = (int*)(sc + NS);             // [NS+1]
    float* ecdf = (float*)(offs + (NS + 1));   // [NG]

    __shared__ float s_pf[32];
    __shared__ float s_pf2[32];
    __shared__ int   s_pi[32];
    __shared__ float s_alpha;

    const int tid = threadIdx.x;
    const int bid = blockIdx.x;
    const int row = bid & (LROWS - 1);
    const int ds  = bid >> 9;
    const size_t base = (size_t)row * NS;
    const float* gx = (ds ? x2 : x1) + base;
    const float* gw = (ds ? w2 : w1) + base;
    float* hout = g_h + (size_t)bid * NS;

    // ---- 1. zero histogram --------------------------------------------------
    for (int i = tid; i <= NS; i += NTHREADS) offs[i] = 0;
    __syncthreads();

    // ---- 2. load, histogram, alpha partials ---------------------------------
    float lx[IPT], lw[IPT];
    float pxw = 0.f, pw = 0.f;
#pragma unroll
    for (int i = 0; i < IPT; i++) {
        int idx = tid + i * NTHREADS;
        float x = gx[idx];
        float w = gw[idx];
        lx[i] = x; lw[i] = w;
        pxw += x * w; pw += w;
        int b = (int)(x * 8192.0f);            // exact order-preserving bucket
        if (b > NS - 1) b = NS - 1;
        atomicAdd(&offs[b + 1], 1);
    }
    {
        int lane = tid & 31, wid = tid >> 5;
        float a = pxw, b = pw;
#pragma unroll
        for (int d = 16; d > 0; d >>= 1) {
            a += __shfl_down_sync(0xffffffffu, a, d);
            b += __shfl_down_sync(0xffffffffu, b, d);
        }
        if (lane == 0) { s_pf[wid] = a; s_pf2[wid] = b; }
        __syncthreads();                       // also fences histogram atomics
        if (tid == 0) {
            float sa = 0.f, sb = 0.f;
#pragma unroll
            for (int k = 0; k < 32; k++) { sa += s_pf[k]; sb += s_pf2[k]; }
            s_alpha = sa / sb - 0.5f;
        }
    }

    // ---- 3. exclusive scan of counts -> bucket offsets ----------------------
    {
        int c[IPT]; int runc = 0;
#pragma unroll
        for (int j = 0; j < IPT; j++) {
            runc += offs[1 + tid * IPT + j];
            c[j] = runc;
        }
        int exc = block_excl_scan_int(runc, tid, s_pi);
#pragma unroll
        for (int j = 0; j < IPT; j++) offs[1 + tid * IPT + j] = exc + c[j];
        __syncthreads();
    }

    // ---- 4. scatter (counting sort); cursors live in ecdf region ------------
    {
        int* cursor = (int*)ecdf;
        for (int b = tid; b < NS; b += NTHREADS) cursor[b] = offs[b];
        __syncthreads();
#pragma unroll
        for (int i = 0; i < IPT; i++) {
            float x = lx[i];
            int b = (int)(x * 8192.0f);
            if (b > NS - 1) b = NS - 1;
            int pos = atomicAdd(&cursor[b], 1);
            sc[pos] = make_float2(x, lw[i]);
        }
        __syncthreads();
    }

    // ---- 5. per-bucket insertion sort (avg occupancy 1) ---------------------
    for (int b = tid; b < NS; b += NTHREADS) {
        int s = offs[b], e = offs[b + 1];
        for (int i = s + 1; i < e; i++) {
            float2 key = sc[i];
            int j = i - 1;
            while (j >= s && sc[j].x > key.x) { sc[j+1] = sc[j]; j--; }
            sc[j+1] = key;
        }
    }
    __syncthreads();

    // ---- 6. cumsum of sorted weights -> cdf (in place, .y lane) -------------
    {
        float v[IPT]; float runf = 0.f;
#pragma unroll
        for (int j = 0; j < IPT; j++) { runf += sc[tid * IPT + j].y; v[j] = runf; }
        float excf = block_excl_scan_float(runf, tid, s_pf);
#pragma unroll
        for (int j = 0; j < IPT; j++) sc[tid * IPT + j].y = excf + v[j];
        __syncthreads();
    }

    // ---- 7. rasterize circular CDF onto 3N grid (GATHER, per-period) --------
    // lower_bound via the exact bucket map: only bucket b needs a strict-less
    // scan (avg occupancy 1). fi is a per-period constant (except j = NG-1).
#pragma unroll
    for (int p = 0; p < 3; p++) {
        const float fip = (float)(p - 1);
#pragma unroll
        for (int jj = 0; jj < GPT_P; jj++) {
            int j = p * NREF + tid + jj * NTHREADS;
            float xn = fmaf((float)j, STEPG, -1.0f);
            float fi = fip;
            if (j == NG - 1) fi = floorf(xn);   // xn ~ 2.0
            float r = xn - fi;
            int b = (int)(r * 8192.0f);
            if (b > NS - 1) b = NS - 1;
            if (b < 0) b = 0;
            int lo = offs[b], hi = offs[b + 1];
            int cnt = lo;
            for (int i = lo; i < hi; i++) cnt += (sc[i].x < r) ? 1 : 0;
            int idx = cnt - 1;
            idx = idx < 0 ? 0 : (idx > NS - 2 ? NS - 2 : idx);
            float2 a = sc[idx];
            float2 bb = sc[idx + 1];
            float t = __fdividef(r - a.x, bb.x - a.x);
            ecdf[j] = fi + fmaf(t, bb.y - a.y, a.y);
        }
    }
    __syncthreads();

    // ---- 8. invert CDF: lockstep EXACT bisection, fully unguarded.
    // Range analysis: min range before iteration k is 24576,12288,...,3,1 --
    // always >= 1, so lo < hi holds for all 15 iterations; guard removed.
    {
        float alpha = s_alpha;
        int   lo[KPT], hi[KPT];
        float yq[KPT];
#pragma unroll
        for (int q = 0; q < KPT; q++) {
            int k = tid + q * NTHREADS;
            yq[q] = (float)k * (1.0f / 8192.0f) - alpha;
            lo[q] = 0; hi[q] = NG;
        }
#pragma unroll
        for (int it = 0; it < 15; it++) {
#pragma unroll
            for (int q = 0; q < KPT; q++) {
                int mid = (lo[q] + hi[q]) >> 1;
                bool c = ecdf[mid] < yq[q];
                lo[q] = c ? mid + 1 : lo[q];
                hi[q] = c ? hi[q] : mid;
            }
        }
#pragma unroll
        for (int q = 0; q < KPT; q++) {
            int k = tid + q * NTHREADS;
            float xk = (float)k * (1.0f / 8192.0f);
            int idx = lo[q] - 1;
            idx = idx < 0 ? 0 : (idx > NG - 2 ? NG - 2 : idx);
            float e0 = ecdf[idx], e1 = ecdf[idx + 1];
            float xn0 = fmaf((float)idx,       STEPG, -1.0f);
            float xn1 = fmaf((float)(idx + 1), STEPG, -1.0f);
            float t = __fdividef(yq[q] - e0, e1 - e0);
            hout[k] = fmaf(t, xn1 - xn0, xn0) - xk;
        }
    }
}

// ---------------------------------------------------------------------------
__global__ void __launch_bounds__(512)
lcot_dist_kernel()
{
    __shared__ float red[512];
    const int row = blockIdx.x, tid = threadIdx.x;
    const float* h1 = g_h + (size_t)row * NS;
    const float* h2 = g_h + (size_t)(LROWS + row) * NS;
    float acc = 0.f;
    for (int i = tid; i < NS; i += 512) {
        float d = fabsf(h2[i] - h1[i]);
        float m = fminf(d, 1.0f - d);
        acc = fmaf(m, m, acc);
    }
    red[tid] = acc;
    __syncthreads();
    for (int s = 256; s > 0; s >>= 1) {
        if (tid < s) red[tid] += red[tid + s];
        __syncthreads();
    }
    if (tid == 0) g_rowsum[row] = red[0];
}

__global__ void lcot_finalize_kernel(float* __restrict__ out)
{
    __shared__ float r[LROWS];
    int t = threadIdx.x;
    r[t] = g_rowsum[t];
    __syncthreads();
    for (int s = LROWS / 2; s > 0; s >>= 1) {
        if (t < s) r[t] += r[t + s];
        __syncthreads();
    }
    if (t == 0) out[0] = sqrtf(r[0] / (float)LROWS);
}

extern "C" void kernel_launch(void* const* d_in, const int* in_sizes, int n_in,
                              void* d_out, int out_size)
{
    const float* x1 = (const float*)d_in[0];
    const float* w1 = (const float*)d_in[1];
    const float* x2 = (const float*)d_in[2];
    const float* w2 = (const float*)d_in[3];
    float* out = (float*)d_out;

    size_t dyn = (size_t)NS * sizeof(float2)
               + (size_t)(NS + 1) * sizeof(int)
               + (size_t)NG * sizeof(float);   // 196612 B

    cudaFuncSetAttribute(lcot_emb_kernel,
                         cudaFuncAttributeMaxDynamicSharedMemorySize, (int)dyn);

    lcot_emb_kernel<<<2 * LROWS, NTHREADS, dyn>>>(x1, w1, x2, w2);
    lcot_dist_kernel<<<LROWS, 512>>>();
    lcot_finalize_kernel<<<1, LROWS>>>(out);
}

// round 7
// speedup vs baseline: 1.0911x; 1.0911x over previous
#include <cuda_runtime.h>
#include <math.h>

#define LROWS    512
#define NS       8192            // samples per row
#define NREF     8192            // reference grid points
#define NG       (3*NREF)        // 24576 circular-CDF grid points
#define NTHREADS 1024
#define IPT      (NS/NTHREADS)   // 8 items per thread
#define KPT      (NREF/NTHREADS) // 8 inversion queries per thread (consecutive)
#define GPT_P    (NREF/NTHREADS) // 8 grid points per thread per period

#define STEPG  (3.0f/24575.0f)
#define INVN   (1.0f/8192.0f)

__device__ float g_rowsum[LROWS];
__device__ float g_h[(size_t)2 * LROWS * NS];   // h1 then h2, 32 MB scratch

// ---------------------------------------------------------------------------
// block-wide exclusive scans (warp shuffle + 32-entry partials)
// ---------------------------------------------------------------------------
__device__ __forceinline__ int block_excl_scan_int(int local_total, int tid, int* s_part)
{
    __syncthreads();
    int lane = tid & 31, wid = tid >> 5;
    int x = local_total;
#pragma unroll
    for (int d = 1; d < 32; d <<= 1) {
        int t = __shfl_up_sync(0xffffffffu, x, d);
        if (lane >= d) x += t;
    }
    if (lane == 31) s_part[wid] = x;
    __syncthreads();
    if (wid == 0) {
        int v = s_part[lane];
        int y = v;
#pragma unroll
        for (int d = 1; d < 32; d <<= 1) {
            int t = __shfl_up_sync(0xffffffffu, y, d);
            if (lane >= d) y += t;
        }
        s_part[lane] = y - v;                  // exclusive warp offsets
    }
    __syncthreads();
    return s_part[wid] + (x - local_total);
}

__device__ __forceinline__ float block_excl_scan_float(float local_total, int tid, float* s_part)
{
    __syncthreads();
    int lane = tid & 31, wid = tid >> 5;
    float x = local_total;
#pragma unroll
    for (int d = 1; d < 32; d <<= 1) {
        float t = __shfl_up_sync(0xffffffffu, x, d);
        if (lane >= d) x += t;
    }
    if (lane == 31) s_part[wid] = x;
    __syncthreads();
    if (wid == 0) {
        float v = s_part[lane];
        float y = v;
#pragma unroll
        for (int d = 1; d < 32; d <<= 1) {
            float t = __shfl_up_sync(0xffffffffu, y, d);
            if (lane >= d) y += t;
        }
        s_part[lane] = y - v;
    }
    __syncthreads();
    return s_part[wid] + (x - local_total);
}

// full exact lower_bound bisection over ecdf[0..NG) -- identical probe path
// to jnp.searchsorted; used for fence queries and the rare unsafe fallback.
__device__ __forceinline__ int full_bisect(const float* ecdf, float y)
{
    int lo = 0, hi = NG;
#pragma unroll
    for (int it = 0; it < 15; it++) {
        int mid = (lo + hi) >> 1;
        bool c = ecdf[mid] < y;
        lo = c ? mid + 1 : lo;
        hi = c ? hi : mid;
    }
    return lo;
}

// ---------------------------------------------------------------------------
// one embedding pass per block: grid = 1024 = 2 datasets x 512 rows
// ---------------------------------------------------------------------------
__global__ void __launch_bounds__(NTHREADS, 1)
lcot_emb_kernel(const float* __restrict__ x1, const float* __restrict__ w1,
                const float* __restrict__ x2, const float* __restrict__ w2)
{
    extern __shared__ char smem_raw[];
    float* xs   = (float*)smem_raw;            // [NS]
    float* cw   = xs + NS;                     // [NS]
    int*   offs = (int*)(cw + NS);             // [NS+1]
    float* ecdf = (float*)(offs + (NS + 1));   // [NG]

    __shared__ float s_pf[32];
    __shared__ float s_pf2[32];
    __shared__ int   s_pi[32];
    __shared__ float s_alpha;

    const int tid = threadIdx.x;
    const int bid = blockIdx.x;
    const int row = bid & (LROWS - 1);
    const int ds  = bid >> 9;
    const size_t base = (size_t)row * NS;
    const float* gx = (ds ? x2 : x1) + base;
    const float* gw = (ds ? w2 : w1) + base;
    float* hout = g_h + (size_t)bid * NS;

    // ---- 1. zero histogram --------------------------------------------------
    for (int i = tid; i <= NS; i += NTHREADS) offs[i] = 0;
    __syncthreads();

    // ---- 2. load, histogram, alpha partials ---------------------------------
    float lx[IPT], lw[IPT];
    float pxw = 0.f, pw = 0.f;
#pragma unroll
    for (int i = 0; i < IPT; i++) {
        int idx = tid + i * NTHREADS;
        float x = gx[idx];
        float w = gw[idx];
        lx[i] = x; lw[i] = w;
        pxw += x * w; pw += w;
        int b = (int)(x * 8192.0f);            // exact order-preserving bucket
        if (b > NS - 1) b = NS - 1;
        atomicAdd(&offs[b + 1], 1);
    }
    {
        int lane = tid & 31, wid = tid >> 5;
        float a = pxw, b = pw;
#pragma unroll
        for (int d = 16; d > 0; d >>= 1) {
            a += __shfl_down_sync(0xffffffffu, a, d);
            b += __shfl_down_sync(0xffffffffu, b, d);
        }
        if (lane == 0) { s_pf[wid] = a; s_pf2[wid] = b; }
        __syncthreads();                       // also fences histogram atomics
        if (tid == 0) {
            float sa = 0.f, sb = 0.f;
#pragma unroll
            for (int k = 0; k < 32; k++) { sa += s_pf[k]; sb += s_pf2[k]; }
            s_alpha = sa / sb - 0.5f;
        }
    }

    // ---- 3. exclusive scan of counts -> bucket offsets ----------------------
    {
        int c[IPT]; int runc = 0;
#pragma unroll
        for (int j = 0; j < IPT; j++) {
            runc += offs[1 + tid * IPT + j];
            c[j] = runc;
        }
        int exc = block_excl_scan_int(runc, tid, s_pi);
#pragma unroll
        for (int j = 0; j < IPT; j++) offs[1 + tid * IPT + j] = exc + c[j];
        __syncthreads();
    }

    // ---- 4. scatter (counting sort); cursors live in ecdf region ------------
    {
        int* cursor = (int*)ecdf;
        for (int b = tid; b < NS; b += NTHREADS) cursor[b] = offs[b];
        __syncthreads();
#pragma unroll
        for (int i = 0; i < IPT; i++) {
            float x = lx[i];
            int b = (int)(x * 8192.0f);
            if (b > NS - 1) b = NS - 1;
            int pos = atomicAdd(&cursor[b], 1);
            xs[pos] = x;
            cw[pos] = lw[i];
        }
        __syncthreads();
    }

    // ---- 5. per-bucket insertion sort (avg occupancy 1) ---------------------
    for (int b = tid; b < NS; b += NTHREADS) {
        int s = offs[b], e = offs[b + 1];
        for (int i = s + 1; i < e; i++) {
            float kx = xs[i], kv = cw[i];
            int j = i - 1;
            while (j >= s && xs[j] > kx) { xs[j+1] = xs[j]; cw[j+1] = cw[j]; j--; }
            xs[j+1] = kx; cw[j+1] = kv;
        }
    }
    __syncthreads();

    // ---- 6. cumsum of sorted weights -> cdf (in place) ----------------------
    {
        float v[IPT]; float runf = 0.f;
#pragma unroll
        for (int j = 0; j < IPT; j++) { runf += cw[tid * IPT + j]; v[j] = runf; }
        float excf = block_excl_scan_float(runf, tid, s_pf);
#pragma unroll
        for (int j = 0; j < IPT; j++) cw[tid * IPT + j] = excf + v[j];
        __syncthreads();
    }

    // ---- 7. rasterize circular CDF onto 3N grid (GATHER, per-period) --------
    // lower_bound via the exact bucket map: only bucket b needs a strict-less
    // scan (avg occupancy 1). fi is a per-period constant; j = NG-1 fixed up
    // afterwards by its owning thread (tid == NTHREADS-1).
#pragma unroll
    for (int p = 0; p < 3; p++) {
        const float fip = (float)(p - 1);
#pragma unroll
        for (int jj = 0; jj < GPT_P; jj++) {
            int j = p * NREF + tid + jj * NTHREADS;
            float xn = fmaf((float)j, STEPG, -1.0f);
            float r = xn - fip;
            int b = (int)(r * 8192.0f);
            if (b > NS - 1) b = NS - 1;
            if (b < 0) b = 0;
            int lo = offs[b], hi = offs[b + 1];
            int cnt = lo;
            for (int i = lo; i < hi; i++) cnt += (xs[i] < r) ? 1 : 0;
            int idx = cnt - 1;
            idx = idx < 0 ? 0 : (idx > NS - 2 ? NS - 2 : idx);
            float x0 = xs[idx], x1v = xs[idx + 1];
            float y0 = cw[idx], y1 = cw[idx + 1];
            float t = __fdividef(r - x0, x1v - x0);
            ecdf[j] = fip + fmaf(t, y1 - y0, y0);
        }
    }
    if (tid == NTHREADS - 1) {      // j = NG-1: fi = floor(xn) (xn ~ 2.0)
        float xn = fmaf((float)(NG - 1), STEPG, -1.0f);
        float fi = floorf(xn);
        float r = xn - fi;
        int b = (int)(r * 8192.0f);
        if (b > NS - 1) b = NS - 1;
        if (b < 0) b = 0;
        int lo = offs[b], hi = offs[b + 1];
        int cnt = lo;
        for (int i = lo; i < hi; i++) cnt += (xs[i] < r) ? 1 : 0;
        int idx = cnt - 1;
        idx = idx < 0 ? 0 : (idx > NS - 2 ? NS - 2 : idx);
        float t = __fdividef(r - xs[idx], xs[idx + 1] - xs[idx]);
        ecdf[NG - 1] = fi + fmaf(t, cw[idx + 1] - cw[idx], cw[idx]);
    }
    __syncthreads();

    // ---- 8. invert CDF: bracketed exact inversion ---------------------------
    // Bisection landings are monotone in y and are always crossing points
    // (ecdf[p-1] < y <= ecdf[p]); ecdf is monotone within each period, its
    // only possible decreases are at indices {8192, 16384, NG-1}. Fence
    // landings (full exact bisection) bracket the 7 intermediate landings;
    // when the bracket avoids all drop indices, the crossing is unique and a
    // restricted bisection yields the IDENTICAL landing. Else: exact fallback.
    {
        float alpha = s_alpha;
        const int k0 = tid * KPT;
        float y0 = (float)k0 * INVN - alpha;
        int posA = full_bisect(ecdf, y0);
        int posB = __shfl_down_sync(0xffffffffu, posA, 1);
        if ((tid & 31) == 31)
            posB = full_bisect(ecdf, (float)(k0 + KPT) * INVN - alpha);

        int pos[KPT];
        pos[0] = posA;
        bool unsafe = (8192  >= posA && 8192  <= posB) ||
                      (16384 >= posA && 16384 <= posB) ||
                      (NG - 1 >= posA && NG - 1 <= posB);
        if (!unsafe) {
            int hi_q[KPT];
#pragma unroll
            for (int q = 1; q < KPT; q++) { pos[q] = posA; hi_q[q] = posB; }
            int w = posB - posA;
            while (w > 0) {
#pragma unroll
                for (int q = 1; q < KPT; q++) {
                    if (pos[q] < hi_q[q]) {
                        int mid = (pos[q] + hi_q[q]) >> 1;
                        bool c = ecdf[mid] < ((float)(k0 + q) * INVN - alpha);
                        pos[q]  = c ? mid + 1 : pos[q];
                        hi_q[q] = c ? hi_q[q] : mid;
                    }
                }
                w >>= 1;
            }
        } else {
#pragma unroll
            for (int q = 1; q < KPT; q++)
                pos[q] = full_bisect(ecdf, (float)(k0 + q) * INVN - alpha);
        }

        float4 outv[KPT / 4];
        float* outf = (float*)outv;
#pragma unroll
        for (int q = 0; q < KPT; q++) {
            int k = k0 + q;
            float xk = (float)k * INVN;
            float yq = xk - alpha;
            int idx = pos[q] - 1;
            idx = idx < 0 ? 0 : (idx > NG - 2 ? NG - 2 : idx);
            float e0 = ecdf[idx], e1 = ecdf[idx + 1];
            float xn0 = fmaf((float)idx,       STEPG, -1.0f);
            float xn1 = fmaf((float)(idx + 1), STEPG, -1.0f);
            float t = __fdividef(yq - e0, e1 - e0);
            outf[q] = fmaf(t, xn1 - xn0, xn0) - xk;
        }
        float4* hv = (float4*)(hout + k0);
        hv[0] = outv[0];
        hv[1] = outv[1];
    }
}

// ---------------------------------------------------------------------------
__global__ void __launch_bounds__(512)
lcot_dist_kernel()
{
    __shared__ float red[512];
    const int row = blockIdx.x, tid = threadIdx.x;
    const float* h1 = g_h + (size_t)row * NS;
    const float* h2 = g_h + (size_t)(LROWS + row) * NS;
    float acc = 0.f;
    for (int i = tid; i < NS; i += 512) {
        float d = fabsf(h2[i] - h1[i]);
        float m = fminf(d, 1.0f - d);
        acc = fmaf(m, m, acc);
    }
    red[tid] = acc;
    __syncthreads();
    for (int s = 256; s > 0; s >>= 1) {
        if (tid < s) red[tid] += red[tid + s];
        __syncthreads();
    }
    if (tid == 0) g_rowsum[row] = red[0];
}

__global__ void lcot_finalize_kernel(float* __restrict__ out)
{
    __shared__ float r[LROWS];
    int t = threadIdx.x;
    r[t] = g_rowsum[t];
    __syncthreads();
    for (int s = LROWS / 2; s > 0; s >>= 1) {
        if (t < s) r[t] += r[t + s];
        __syncthreads();
    }
    if (t == 0) out[0] = sqrtf(r[0] / (float)LROWS);
}

extern "C" void kernel_launch(void* const* d_in, const int* in_sizes, int n_in,
                              void* d_out, int out_size)
{
    const float* x1 = (const float*)d_in[0];
    const float* w1 = (const float*)d_in[1];
    const float* x2 = (const float*)d_in[2];
    const float* w2 = (const float*)d_in[3];
    float* out = (float*)d_out;

    size_t dyn = (size_t)(2 * NS) * sizeof(float)
               + (size_t)(NS + 1) * sizeof(int)
               + (size_t)NG * sizeof(float);   // 196612 B

    cudaFuncSetAttribute(lcot_emb_kernel,
                         cudaFuncAttributeMaxDynamicSharedMemorySize, (int)dyn);

    lcot_emb_kernel<<<2 * LROWS, NTHREADS, dyn>>>(x1, w1, x2, w2);
    lcot_dist_kernel<<<LROWS, 512>>>();
    lcot_finalize_kernel<<<1, LROWS>>>(out);
}

// round 9
// speedup vs baseline: 1.1998x; 1.0996x over previous
#include <cuda_runtime.h>
#include <math.h>

#define LROWS    512
#define NS       8192            // samples per row
#define NREF     8192            // reference grid points
#define NG       (3*NREF)        // 24576 circular-CDF grid points
#define NTHREADS 1024
#define IPT      (NS/NTHREADS)   // 8 items per thread
#define KPT      (NREF/NTHREADS) // 8 inversion queries per thread (consecutive)

#define STEPG  (3.0f/24575.0f)
#define INVN   (1.0f/8192.0f)

__device__ float g_rowsum[LROWS];
__device__ float g_h[(size_t)2 * LROWS * NS];   // h1 then h2, 32 MB scratch

// ---------------------------------------------------------------------------
// block-wide exclusive scans (warp shuffle + 32-entry partials)
// ---------------------------------------------------------------------------
__device__ __forceinline__ int block_excl_scan_int(int local_total, int tid, int* s_part)
{
    __syncthreads();
    int lane = tid & 31, wid = tid >> 5;
    int x = local_total;
#pragma unroll
    for (int d = 1; d < 32; d <<= 1) {
        int t = __shfl_up_sync(0xffffffffu, x, d);
        if (lane >= d) x += t;
    }
    if (lane == 31) s_part[wid] = x;
    __syncthreads();
    if (wid == 0) {
        int v = s_part[lane];
        int y = v;
#pragma unroll
        for (int d = 1; d < 32; d <<= 1) {
            int t = __shfl_up_sync(0xffffffffu, y, d);
            if (lane >= d) y += t;
        }
        s_part[lane] = y - v;                  // exclusive warp offsets
    }
    __syncthreads();
    return s_part[wid] + (x - local_total);
}

__device__ __forceinline__ float block_excl_scan_float(float local_total, int tid, float* s_part)
{
    __syncthreads();
    int lane = tid & 31, wid = tid >> 5;
    float x = local_total;
#pragma unroll
    for (int d = 1; d < 32; d <<= 1) {
        float t = __shfl_up_sync(0xffffffffu, x, d);
        if (lane >= d) x += t;
    }
    if (lane == 31) s_part[wid] = x;
    __syncthreads();
    if (wid == 0) {
        float v = s_part[lane];
        float y = v;
#pragma unroll
        for (int d = 1; d < 32; d <<= 1) {
            float t = __shfl_up_sync(0xffffffffu, y, d);
            if (lane >= d) y += t;
        }
        s_part[lane] = y - v;
    }
    __syncthreads();
    return s_part[wid] + (x - local_total);
}

// exact per-grid-point circular-CDF value (identical arithmetic to the
// materializing raster of prior rounds -- bit-for-bit).
__device__ __forceinline__ float eval_ecdf(int j, const float* xs, const float* cw,
                                           const int* offs)
{
    float xn = fmaf((float)j, STEPG, -1.0f);
    float fi = (float)((j >> 13) - 1);         // period constant
    if (j == NG - 1) fi = floorf(xn);          // xn ~ 2.0 endpoint
    float r = xn - fi;
    int b = (int)(r * 8192.0f);
    if (b > NS - 1) b = NS - 1;
    if (b < 0) b = 0;
    int lo = offs[b], hi = offs[b + 1];
    int cnt = lo;
    for (int i = lo; i < hi; i++) cnt += (xs[i] < r) ? 1 : 0;
    int idx = cnt - 1;
    idx = idx < 0 ? 0 : (idx > NS - 2 ? NS - 2 : idx);
    float t = __fdividef(r - xs[idx], xs[idx + 1] - xs[idx]);
    return fi + fmaf(t, cw[idx + 1] - cw[idx], cw[idx]);
}

// full exact lower_bound bisection over rasterized ecdf -- identical probe
// path to jnp.searchsorted.
__device__ __forceinline__ int full_bisect(const float* ecdf, float y)
{
    int lo = 0, hi = NG;
#pragma unroll
    for (int it = 0; it < 15; it++) {
        int mid = (lo + hi) >> 1;
        bool c = ecdf[mid] < y;
        lo = c ? mid + 1 : lo;
        hi = c ? hi : mid;
    }
    return lo;
}

// value-driven bisection with on-the-fly evaluation; stashes every probed
// value into ecdf[]. Visits exactly the fixed-tree nodes containing its
// landing, so the stashed indices cover all out-of-range probes of later
// searches (covering argument: any probe m outside [jlo, jhi] made by a query
// landing inside lies on the jlo-path or jhi-path of the fixed bisection tree).
__device__ __forceinline__ int bisect_eval_stash(float* ecdf, const float* xs,
                                                 const float* cw, const int* offs,
                                                 float y)
{
    int lo = 0, hi = NG;
#pragma unroll
    for (int it = 0; it < 15; it++) {
        int mid = (lo + hi) >> 1;
        float v = eval_ecdf(mid, xs, cw, offs);
        ecdf[mid] = v;
        bool c = v < y;
        lo = c ? mid + 1 : lo;
        hi = c ? hi : mid;
    }
    return lo;
}

// ---------------------------------------------------------------------------
// one embedding pass per block: grid = 1024 = 2 datasets x 512 rows
// ---------------------------------------------------------------------------
__global__ void __launch_bounds__(NTHREADS, 1)
lcot_emb_kernel(const float* __restrict__ x1, const float* __restrict__ w1,
                const float* __restrict__ x2, const float* __restrict__ w2)
{
    extern __shared__ char smem_raw[];
    float* xs   = (float*)smem_raw;            // [NS]
    float* cw   = xs + NS;                     // [NS]
    int*   offs = (int*)(cw + NS);             // [NS+1]
    float* ecdf = (float*)(offs + (NS + 1));   // [NG]

    __shared__ float s_pf[32];
    __shared__ float s_pf2[32];
    __shared__ int   s_pi[32];
    __shared__ float s_alpha;
    __shared__ int   s_jlo, s_jhi;

    const int tid = threadIdx.x;
    const int bid = blockIdx.x;
    const int row = bid & (LROWS - 1);
    const int ds  = bid >> 9;
    const size_t base = (size_t)row * NS;
    const float* gx = (ds ? x2 : x1) + base;
    const float* gw = (ds ? w2 : w1) + base;
    float* hout = g_h + (size_t)bid * NS;

    // ---- 1. zero histogram --------------------------------------------------
    for (int i = tid; i <= NS; i += NTHREADS) offs[i] = 0;
    __syncthreads();

    // ---- 2. load, histogram, alpha partials ---------------------------------
    float lx[IPT], lw[IPT];
    float pxw = 0.f, pw = 0.f;
#pragma unroll
    for (int i = 0; i < IPT; i++) {
        int idx = tid + i * NTHREADS;
        float x = gx[idx];
        float w = gw[idx];
        lx[i] = x; lw[i] = w;
        pxw += x * w; pw += w;
        int b = (int)(x * 8192.0f);            // exact order-preserving bucket
        if (b > NS - 1) b = NS - 1;
        atomicAdd(&offs[b + 1], 1);
    }
    {
        int lane = tid & 31, wid = tid >> 5;
        float a = pxw, b = pw;
#pragma unroll
        for (int d = 16; d > 0; d >>= 1) {
            a += __shfl_down_sync(0xffffffffu, a, d);
            b += __shfl_down_sync(0xffffffffu, b, d);
        }
        if (lane == 0) { s_pf[wid] = a; s_pf2[wid] = b; }
        __syncthreads();                       // also fences histogram atomics
        if (tid == 0) {
            float sa = 0.f, sb = 0.f;
#pragma unroll
            for (int k = 0; k < 32; k++) { sa += s_pf[k]; sb += s_pf2[k]; }
            s_alpha = sa / sb - 0.5f;
        }
    }

    // ---- 3. exclusive scan of counts -> bucket offsets ----------------------
    {
        int c[IPT]; int runc = 0;
#pragma unroll
        for (int j = 0; j < IPT; j++) {
            runc += offs[1 + tid * IPT + j];
            c[j] = runc;
        }
        int exc = block_excl_scan_int(runc, tid, s_pi);
#pragma unroll
        for (int j = 0; j < IPT; j++) offs[1 + tid * IPT + j] = exc + c[j];
        __syncthreads();
    }

    // ---- 4. scatter (counting sort); cursors live in ecdf region ------------
    {
        int* cursor = (int*)ecdf;
        for (int b = tid; b < NS; b += NTHREADS) cursor[b] = offs[b];
        __syncthreads();
#pragma unroll
        for (int i = 0; i < IPT; i++) {
            float x = lx[i];
            int b = (int)(x * 8192.0f);
            if (b > NS - 1) b = NS - 1;
            int pos = atomicAdd(&cursor[b], 1);
            xs[pos] = x;
            cw[pos] = lw[i];
        }
        __syncthreads();
    }

    // ---- 5. per-bucket insertion sort (avg occupancy 1) ---------------------
    for (int b = tid; b < NS; b += NTHREADS) {
        int s = offs[b], e = offs[b + 1];
        for (int i = s + 1; i < e; i++) {
            float kx = xs[i], kv = cw[i];
            int j = i - 1;
            while (j >= s && xs[j] > kx) { xs[j+1] = xs[j]; cw[j+1] = cw[j]; j--; }
            xs[j+1] = kx; cw[j+1] = kv;
        }
    }
    __syncthreads();

    // ---- 6. cumsum of sorted weights -> cdf (in place) ----------------------
    {
        float v[IPT]; float runf = 0.f;
#pragma unroll
        for (int j = 0; j < IPT; j++) { runf += cw[tid * IPT + j]; v[j] = runf; }
        float excf = block_excl_scan_float(runf, tid, s_pf);
#pragma unroll
        for (int j = 0; j < IPT; j++) cw[tid * IPT + j] = excf + v[j];
        __syncthreads();
    }

    // ---- 7a. landing bounds via stashing mini-bisections --------------------
    // jlo = landing of smallest query y(0), jhi = landing of largest y(NREF-1).
    // All other landings lie in [jlo, jhi] (landing monotone in y); all probes
    // outside [jlo, jhi] lie on these two paths and are stashed here.
    if (tid == 0)
        s_jlo = bisect_eval_stash(ecdf, xs, cw, offs, 0.0f - s_alpha);
    else if (tid == 32)
        s_jhi = bisect_eval_stash(ecdf, xs, cw, offs,
                                  (float)(NREF - 1) * INVN - s_alpha);
    __syncthreads();

    // ---- 7b. raster only the live window [jlo-1, jhi] -----------------------
    {
        int jstart = s_jlo - 1; if (jstart < 0) jstart = 0;
        int jend   = s_jhi;     if (jend > NG - 1) jend = NG - 1;
        for (int j = jstart + tid; j <= jend; j += NTHREADS)
            ecdf[j] = eval_ecdf(j, xs, cw, offs);
    }
    __syncthreads();

    // ---- 8. invert CDF: bracketed exact inversion ---------------------------
    // Fence landings (full exact bisection) bracket the 7 intermediate
    // landings; when the bracket avoids the possible non-monotone indices
    // {8192, 16384, NG-1}, a restricted bisection yields the IDENTICAL
    // landing. Else: exact full-bisect fallback.
    {
        float alpha = s_alpha;
        const int k0 = tid * KPT;
        float y0 = (float)k0 * INVN - alpha;
        int posA = full_bisect(ecdf, y0);
        int posB = __shfl_down_sync(0xffffffffu, posA, 1);
        if ((tid & 31) == 31)
            posB = full_bisect(ecdf, (float)(k0 + KPT) * INVN - alpha);

        int pos[KPT];
        pos[0] = posA;
        bool unsafe = (8192  >= posA && 8192  <= posB) ||
                      (16384 >= posA && 16384 <= posB) ||
                      (NG - 1 >= posA && NG - 1 <= posB);
        if (!unsafe) {
            int hi_q[KPT];
#pragma unroll
            for (int q = 1; q < KPT; q++) { pos[q] = posA; hi_q[q] = posB; }
            int w = posB - posA;
            while (w > 0) {
#pragma unroll
                for (int q = 1; q < KPT; q++) {
                    if (pos[q] < hi_q[q]) {
                        int mid = (pos[q] + hi_q[q]) >> 1;
                        bool c = ecdf[mid] < ((float)(k0 + q) * INVN - alpha);
                        pos[q]  = c ? mid + 1 : pos[q];
                        hi_q[q] = c ? hi_q[q] : mid;
                    }
                }
                w >>= 1;
            }
        } else {
#pragma unroll
            for (int q = 1; q < KPT; q++)
                pos[q] = full_bisect(ecdf, (float)(k0 + q) * INVN - alpha);
        }

        float4 outv[KPT / 4];
        float* outf = (float*)outv;
#pragma unroll
        for (int q = 0; q < KPT; q++) {
            int k = k0 + q;
            float xk = (float)k * INVN;
            float yq = xk - alpha;
            int idx = pos[q] - 1;
            idx = idx < 0 ? 0 : (idx > NG - 2 ? NG - 2 : idx);
            float e0 = ecdf[idx], e1 = ecdf[idx + 1];
            float xn0 = fmaf((float)idx,       STEPG, -1.0f);
            float xn1 = fmaf((float)(idx + 1), STEPG, -1.0f);
            float t = __fdividef(yq - e0, e1 - e0);
            outf[q] = fmaf(t, xn1 - xn0, xn0) - xk;
        }
        float4* hv = (float4*)(hout + k0);
        hv[0] = outv[0];
        hv[1] = outv[1];
    }
}

// ---------------------------------------------------------------------------
__global__ void __launch_bounds__(512)
lcot_dist_kernel()
{
    __shared__ float red[512];
    const int row = blockIdx.x, tid = threadIdx.x;
    const float* h1 = g_h + (size_t)row * NS;
    const float* h2 = g_h + (size_t)(LROWS + row) * NS;
    float acc = 0.f;
    for (int i = tid; i < NS; i += 512) {
        float d = fabsf(h2[i] - h1[i]);
        float m = fminf(d, 1.0f - d);
        acc = fmaf(m, m, acc);
    }
    red[tid] = acc;
    __syncthreads();
    for (int s = 256; s > 0; s >>= 1) {
        if (tid < s) red[tid] += red[tid + s];
        __syncthreads();
    }
    if (tid == 0) g_rowsum[row] = red[0];
}

__global__ void lcot_finalize_kernel(float* __restrict__ out)
{
    __shared__ float r[LROWS];
    int t = threadIdx.x;
    r[t] = g_rowsum[t];
    __syncthreads();
    for (int s = LROWS / 2; s > 0; s >>= 1) {
        if (t < s) r[t] += r[t + s];
        __syncthreads();
    }
    if (t == 0) out[0] = sqrtf(r[0] / (float)LROWS);
}

extern "C" void kernel_launch(void* const* d_in, const int* in_sizes, int n_in,
                              void* d_out, int out_size)
{
    const float* x1 = (const float*)d_in[0];
    const float* w1 = (const float*)d_in[1];
    const float* x2 = (const float*)d_in[2];
    const float* w2 = (const float*)d_in[3];
    float* out = (float*)d_out;

    size_t dyn = (size_t)(2 * NS) * sizeof(float)
               + (size_t)(NS + 1) * sizeof(int)
               + (size_t)NG * sizeof(float);   // 196612 B

    cudaFuncSetAttribute(lcot_emb_kernel,
                         cudaFuncAttributeMaxDynamicSharedMemorySize, (int)dyn);

    lcot_emb_kernel<<<2 * LROWS, NTHREADS, dyn>>>(x1, w1, x2, w2);
    lcot_dist_kernel<<<LROWS, 512>>>();
    lcot_finalize_kernel<<<1, LROWS>>>(out);
}

// round 10
// speedup vs baseline: 1.2636x; 1.0532x over previous
#include <cuda_runtime.h>
#include <math.h>

#define LROWS    512
#define NS       8192            // samples per row
#define NREF     8192            // reference grid points
#define NG       (3*NREF)        // 24576 circular-CDF grid points
#define NTHREADS 1024
#define IPT      (NS/NTHREADS)   // 8 items per thread
#define KPT      (NREF/NTHREADS) // 8 inversion queries per thread (consecutive)

#define STEPG  (3.0f/24575.0f)
#define INVN   (1.0f/8192.0f)

__device__ float g_rowsum[LROWS];
__device__ int   g_done[LROWS];                 // zero-init; self-resetting
__device__ float g_h[(size_t)2 * LROWS * NS];   // h1 then h2, 32 MB scratch

// ---------------------------------------------------------------------------
// block-wide exclusive scans (warp shuffle + 32-entry partials)
// ---------------------------------------------------------------------------
__device__ __forceinline__ int block_excl_scan_int(int local_total, int tid, int* s_part)
{
    __syncthreads();
    int lane = tid & 31, wid = tid >> 5;
    int x = local_total;
#pragma unroll
    for (int d = 1; d < 32; d <<= 1) {
        int t = __shfl_up_sync(0xffffffffu, x, d);
        if (lane >= d) x += t;
    }
    if (lane == 31) s_part[wid] = x;
    __syncthreads();
    if (wid == 0) {
        int v = s_part[lane];
        int y = v;
#pragma unroll
        for (int d = 1; d < 32; d <<= 1) {
            int t = __shfl_up_sync(0xffffffffu, y, d);
            if (lane >= d) y += t;
        }
        s_part[lane] = y - v;                  // exclusive warp offsets
    }
    __syncthreads();
    return s_part[wid] + (x - local_total);
}

__device__ __forceinline__ float block_excl_scan_float(float local_total, int tid, float* s_part)
{
    __syncthreads();
    int lane = tid & 31, wid = tid >> 5;
    float x = local_total;
#pragma unroll
    for (int d = 1; d < 32; d <<= 1) {
        float t = __shfl_up_sync(0xffffffffu, x, d);
        if (lane >= d) x += t;
    }
    if (lane == 31) s_part[wid] = x;
    __syncthreads();
    if (wid == 0) {
        float v = s_part[lane];
        float y = v;
#pragma unroll
        for (int d = 1; d < 32; d <<= 1) {
            float t = __shfl_up_sync(0xffffffffu, y, d);
            if (lane >= d) y += t;
        }
        s_part[lane] = y - v;
    }
    __syncthreads();
    return s_part[wid] + (x - local_total);
}

// exact per-grid-point circular-CDF value (identical arithmetic across all
// call sites -- bit-for-bit, so racy duplicate writes are benign).
__device__ __forceinline__ float eval_ecdf(int j, const float* xs, const float* cw,
                                           const int* offs)
{
    float xn = fmaf((float)j, STEPG, -1.0f);
    float fi = (float)((j >> 13) - 1);         // period constant
    if (j == NG - 1) fi = floorf(xn);          // xn ~ 2.0 endpoint
    float r = xn - fi;
    int b = (int)(r * 8192.0f);
    if (b > NS - 1) b = NS - 1;
    if (b < 0) b = 0;
    int lo = offs[b], hi = offs[b + 1];
    int cnt = lo;
    for (int i = lo; i < hi; i++) cnt += (xs[i] < r) ? 1 : 0;
    int idx = cnt - 1;
    idx = idx < 0 ? 0 : (idx > NS - 2 ? NS - 2 : idx);
    float t = __fdividef(r - xs[idx], xs[idx + 1] - xs[idx]);
    return fi + fmaf(t, cw[idx + 1] - cw[idx], cw[idx]);
}

// full exact lower_bound bisection over rasterized ecdf -- identical probe
// path to jnp.searchsorted.
__device__ __forceinline__ int full_bisect(const float* ecdf, float y)
{
    int lo = 0, hi = NG;
#pragma unroll
    for (int it = 0; it < 15; it++) {
        int mid = (lo + hi) >> 1;
        bool c = ecdf[mid] < y;
        lo = c ? mid + 1 : lo;
        hi = c ? hi : mid;
    }
    return lo;
}

// value-driven bisection with on-the-fly evaluation; stashes every probed
// value into ecdf[]. Visits exactly the fixed-tree nodes containing its
// landing, so the stashed indices cover every probe outside [jlo, jhi] made
// by any query whose landing lies inside [jlo, jhi] (covering argument: such
// a probe's node interval contains both the probe and jlo (or jhi), hence is
// the unique node on the jlo- (jhi-) path at that depth).
__device__ __forceinline__ int bisect_eval_stash(float* ecdf, const float* xs,
                                                 const float* cw, const int* offs,
                                                 float y)
{
    int lo = 0, hi = NG;
#pragma unroll
    for (int it = 0; it < 15; it++) {
        int mid = (lo + hi) >> 1;
        float v = eval_ecdf(mid, xs, cw, offs);
        ecdf[mid] = v;
        bool c = v < y;
        lo = c ? mid + 1 : lo;
        hi = c ? hi : mid;
    }
    return lo;
}

// ---------------------------------------------------------------------------
// one embedding pass per block: grid = 1024 = 2 datasets x 512 rows
// ---------------------------------------------------------------------------
__global__ void __launch_bounds__(NTHREADS, 1)
lcot_emb_kernel(const float* __restrict__ x1, const float* __restrict__ w1,
                const float* __restrict__ x2, const float* __restrict__ w2)
{
    extern __shared__ char smem_raw[];
    float* xs   = (float*)smem_raw;            // [NS]
    float* cw   = xs + NS;                     // [NS]
    int*   offs = (int*)(cw + NS);             // [NS+1]
    float* ecdf = (float*)(offs + (NS + 1));   // [NG]

    __shared__ float s_pf[32];
    __shared__ float s_pf2[32];
    __shared__ int   s_pi[32];
    __shared__ float s_alpha;
    __shared__ int   s_jlo, s_jhi;
    __shared__ int   s_second;

    const int tid = threadIdx.x;
    const int bid = blockIdx.x;
    const int row = bid & (LROWS - 1);
    const int ds  = bid >> 9;
    const size_t base = (size_t)row * NS;
    const float* gx = (ds ? x2 : x1) + base;
    const float* gw = (ds ? w2 : w1) + base;
    float* hout = g_h + (size_t)bid * NS;

    // ---- 1. zero histogram --------------------------------------------------
    for (int i = tid; i <= NS; i += NTHREADS) offs[i] = 0;
    __syncthreads();

    // ---- 2. load, histogram, alpha partials ---------------------------------
    float lx[IPT], lw[IPT];
    float pxw = 0.f, pw = 0.f;
#pragma unroll
    for (int i = 0; i < IPT; i++) {
        int idx = tid + i * NTHREADS;
        float x = gx[idx];
        float w = gw[idx];
        lx[i] = x; lw[i] = w;
        pxw += x * w; pw += w;
        int b = (int)(x * 8192.0f);            // exact order-preserving bucket
        if (b > NS - 1) b = NS - 1;
        atomicAdd(&offs[b + 1], 1);
    }
    {
        int lane = tid & 31, wid = tid >> 5;
        float a = pxw, b = pw;
#pragma unroll
        for (int d = 16; d > 0; d >>= 1) {
            a += __shfl_down_sync(0xffffffffu, a, d);
            b += __shfl_down_sync(0xffffffffu, b, d);
        }
        if (lane == 0) { s_pf[wid] = a; s_pf2[wid] = b; }
        __syncthreads();                       // also fences histogram atomics
        if (tid == 0) {
            float sa = 0.f, sb = 0.f;
#pragma unroll
            for (int k = 0; k < 32; k++) { sa += s_pf[k]; sb += s_pf2[k]; }
            s_alpha = sa / sb - 0.5f;
        }
    }

    // ---- 3. exclusive scan of counts -> bucket offsets ----------------------
    {
        int c[IPT]; int runc = 0;
#pragma unroll
        for (int j = 0; j < IPT; j++) {
            runc += offs[1 + tid * IPT + j];
            c[j] = runc;
        }
        int exc = block_excl_scan_int(runc, tid, s_pi);
#pragma unroll
        for (int j = 0; j < IPT; j++) offs[1 + tid * IPT + j] = exc + c[j];
        __syncthreads();
    }

    // ---- 4. scatter (counting sort); cursors live in ecdf region ------------
    {
        int* cursor = (int*)ecdf;
        for (int b = tid; b < NS; b += NTHREADS) cursor[b] = offs[b];
        __syncthreads();
#pragma unroll
        for (int i = 0; i < IPT; i++) {
            float x = lx[i];
            int b = (int)(x * 8192.0f);
            if (b > NS - 1) b = NS - 1;
            int pos = atomicAdd(&cursor[b], 1);
            xs[pos] = x;
            cw[pos] = lw[i];
        }
        __syncthreads();
    }

    // ---- 5. per-bucket insertion sort (avg occupancy 1) ---------------------
    for (int b = tid; b < NS; b += NTHREADS) {
        int s = offs[b], e = offs[b + 1];
        for (int i = s + 1; i < e; i++) {
            float kx = xs[i], kv = cw[i];
            int j = i - 1;
            while (j >= s && xs[j] > kx) { xs[j+1] = xs[j]; cw[j+1] = cw[j]; j--; }
            xs[j+1] = kx; cw[j+1] = kv;
        }
    }
    __syncthreads();

    // ---- 6. cumsum of sorted weights -> cdf (in place) ----------------------
    {
        float v[IPT]; float runf = 0.f;
#pragma unroll
        for (int j = 0; j < IPT; j++) { runf += cw[tid * IPT + j]; v[j] = runf; }
        float excf = block_excl_scan_float(runf, tid, s_pf);
#pragma unroll
        for (int j = 0; j < IPT; j++) cw[tid * IPT + j] = excf + v[j];
        __syncthreads();
    }

    // ---- 7a. overlap: stashing mini-bisections || speculative raster --------
    // jlo = bisect landing of y(0), jhi = of y(NREF-1); all query landings lie
    // in [jlo, jhi] and all out-of-window probes are stashed by the two paths.
    // Meanwhile warps 2..31 raster an alpha-predicted window (margins cover
    // the ~KS-scale cdf deviation); duplicate writes are bit-identical.
    const float alpha_r = s_alpha;
    int spec_lo, spec_hi;
    {
        int est = (int)((1.0f - alpha_r) * (24575.0f / 3.0f));
        spec_lo = est - 288;         if (spec_lo < 0) spec_lo = 0;
        spec_hi = est + NS + 576;    if (spec_hi > NG - 1) spec_hi = NG - 1;
        if (tid == 0)
            s_jlo = bisect_eval_stash(ecdf, xs, cw, offs, 0.0f - alpha_r);
        else if (tid == 32)
            s_jhi = bisect_eval_stash(ecdf, xs, cw, offs,
                                      (float)(NREF - 1) * INVN - alpha_r);
        else if (tid >= 64) {
            for (int j = spec_lo + (tid - 64); j <= spec_hi; j += NTHREADS - 64)
                ecdf[j] = eval_ecdf(j, xs, cw, offs);
        }
    }
    __syncthreads();

    // ---- 7b. gap fill: [jlo-1, jhi] minus the speculative window ------------
    {
        int jstart = s_jlo - 1; if (jstart < 0) jstart = 0;
        int jend   = s_jhi;     if (jend > NG - 1) jend = NG - 1;
        for (int j = jstart + tid; j <= jend; j += NTHREADS)
            if (j < spec_lo || j > spec_hi)
                ecdf[j] = eval_ecdf(j, xs, cw, offs);
    }
    __syncthreads();

    // ---- 8. invert CDF: bracketed exact inversion ---------------------------
    // Fence landings bracket the 7 intermediate landings (landings monotone in
    // y); when the bracket avoids the possible non-monotone indices
    // {8192, 16384, NG-1}, a restricted bisection yields the IDENTICAL
    // landing. Else: exact full-bisect fallback. tid 1023's upper fence is
    // s_jhi itself (= exact landing of y(NREF-1)); y(NREF) is NOT probed.
    {
        const int k0 = tid * KPT;
        float y0 = (float)k0 * INVN - alpha_r;
        int posA = full_bisect(ecdf, y0);
        int posB = __shfl_down_sync(0xffffffffu, posA, 1);
        if ((tid & 31) == 31) {
            posB = (tid == NTHREADS - 1)
                 ? s_jhi
                 : full_bisect(ecdf, (float)(k0 + KPT) * INVN - alpha_r);
        }

        int pos[KPT];
        pos[0] = posA;
        bool unsafe = (8192  >= posA && 8192  <= posB) ||
                      (16384 >= posA && 16384 <= posB) ||
                      (NG - 1 >= posA && NG - 1 <= posB);
        if (!unsafe) {
            int hi_q[KPT];
#pragma unroll
            for (int q = 1; q < KPT; q++) { pos[q] = posA; hi_q[q] = posB; }
            int w = posB - posA;
            while (w > 0) {
#pragma unroll
                for (int q = 1; q < KPT; q++) {
                    if (pos[q] < hi_q[q]) {
                        int mid = (pos[q] + hi_q[q]) >> 1;
                        bool c = ecdf[mid] < ((float)(k0 + q) * INVN - alpha_r);
                        pos[q]  = c ? mid + 1 : pos[q];
                        hi_q[q] = c ? hi_q[q] : mid;
                    }
                }
                w >>= 1;
            }
        } else {
#pragma unroll
            for (int q = 1; q < KPT; q++)
                pos[q] = full_bisect(ecdf, (float)(k0 + q) * INVN - alpha_r);
        }

        float4 outv[KPT / 4];
        float* outf = (float*)outv;
#pragma unroll
        for (int q = 0; q < KPT; q++) {
            int k = k0 + q;
            float xk = (float)k * INVN;
            float yq = xk - alpha_r;
            int idx = pos[q] - 1;
            idx = idx < 0 ? 0 : (idx > NG - 2 ? NG - 2 : idx);
            float e0 = ecdf[idx], e1 = ecdf[idx + 1];
            float xn0 = fmaf((float)idx,       STEPG, -1.0f);
            float xn1 = fmaf((float)(idx + 1), STEPG, -1.0f);
            float t = __fdividef(yq - e0, e1 - e0);
            outf[q] = fmaf(t, xn1 - xn0, xn0) - xk;
        }
        float4* hv = (float4*)(hout + k0);
        hv[0] = outv[0];
        hv[1] = outv[1];
    }

    // ---- 9. fused distance: second block to finish this row computes --------
    // Release: fence h-writes, then atomic arrive. Acquire: atomic, fence,
    // then read both h arrays. Result is a fixed-order tree reduction over
    // global data -- identical regardless of which block wins the race.
    __threadfence();
    __syncthreads();                           // all h writes of block done
    if (tid == 0) {
        int old = atomicAdd(&g_done[row], 1);
        s_second = (old == 1);
        if (old == 1) g_done[row] = 0;         // self-reset for graph replays
    }
    __syncthreads();
    if (s_second) {
        __threadfence();                       // acquire partner's h writes
        const float* hA = g_h + (size_t)row * NS;
        const float* hB = g_h + (size_t)(LROWS + row) * NS;
        float acc = 0.f;
        for (int i = tid; i < NS; i += NTHREADS) {
            float d = fabsf(hB[i] - hA[i]);
            float m = fminf(d, 1.0f - d);
            acc = fmaf(m, m, acc);
        }
        int lane = tid & 31, wid = tid >> 5;
#pragma unroll
        for (int d = 16; d > 0; d >>= 1)
            acc += __shfl_down_sync(0xffffffffu, acc, d);
        if (lane == 0) s_pf[wid] = acc;
        __syncthreads();
        if (tid == 0) {
            float s = 0.f;
#pragma unroll
            for (int k = 0; k < 32; k++) s += s_pf[k];
            g_rowsum[row] = s;
        }
    }
}

// ---------------------------------------------------------------------------
__global__ void lcot_finalize_kernel(float* __restrict__ out)
{
    __shared__ float r[LROWS];
    int t = threadIdx.x;
    r[t] = g_rowsum[t];
    __syncthreads();
    for (int s = LROWS / 2; s > 0; s >>= 1) {
        if (t < s) r[t] += r[t + s];
        __syncthreads();
    }
    if (t == 0) out[0] = sqrtf(r[0] / (float)LROWS);
}

extern "C" void kernel_launch(void* const* d_in, const int* in_sizes, int n_in,
                              void* d_out, int out_size)
{
    const float* x1 = (const float*)d_in[0];
    const float* w1 = (const float*)d_in[1];
    const float* x2 = (const float*)d_in[2];
    const float* w2 = (const float*)d_in[3];
    float* out = (float*)d_out;

    size_t dyn = (size_t)(2 * NS) * sizeof(float)
               + (size_t)(NS + 1) * sizeof(int)
               + (size_t)NG * sizeof(float);   // 196612 B

    cudaFuncSetAttribute(lcot_emb_kernel,
                         cudaFuncAttributeMaxDynamicSharedMemorySize, (int)dyn);

    lcot_emb_kernel<<<2 * LROWS, NTHREADS, dyn>>>(x1, w1, x2, w2);
    lcot_finalize_kernel<<<1, LROWS>>>(out);
}

// round 12
// speedup vs baseline: 1.3103x; 1.0370x over previous
#include <cuda_runtime.h>
#include <math.h>

#define LROWS    512
#define NS       8192            // samples per row
#define NREF     8192            // reference grid points
#define NG       (3*NREF)        // 24576 circular-CDF grid points
#define NTHREADS 1024
#define IPT      (NS/NTHREADS)   // 8 items per thread
#define KPT      (NREF/NTHREADS) // 8 inversion queries per thread (consecutive)

#define STEPG  (3.0f/24575.0f)
#define INVN   (1.0f/8192.0f)

__device__ float g_rowsum[LROWS];
__device__ int   g_done[LROWS];                 // zero-init; self-resetting
__device__ int   g_nrows;                       // zero-init; self-resetting
__device__ float g_h[(size_t)2 * LROWS * NS];   // h1 then h2, 32 MB scratch

// ---------------------------------------------------------------------------
// block-wide exclusive scans (warp shuffle + 32-entry partials)
// ---------------------------------------------------------------------------
__device__ __forceinline__ int block_excl_scan_int(int local_total, int tid, int* s_part)
{
    __syncthreads();
    int lane = tid & 31, wid = tid >> 5;
    int x = local_total;
#pragma unroll
    for (int d = 1; d < 32; d <<= 1) {
        int t = __shfl_up_sync(0xffffffffu, x, d);
        if (lane >= d) x += t;
    }
    if (lane == 31) s_part[wid] = x;
    __syncthreads();
    if (wid == 0) {
        int v = s_part[lane];
        int y = v;
#pragma unroll
        for (int d = 1; d < 32; d <<= 1) {
            int t = __shfl_up_sync(0xffffffffu, y, d);
            if (lane >= d) y += t;
        }
        s_part[lane] = y - v;                  // exclusive warp offsets
    }
    __syncthreads();
    return s_part[wid] + (x - local_total);
}

__device__ __forceinline__ float block_excl_scan_float(float local_total, int tid, float* s_part)
{
    __syncthreads();
    int lane = tid & 31, wid = tid >> 5;
    float x = local_total;
#pragma unroll
    for (int d = 1; d < 32; d <<= 1) {
        float t = __shfl_up_sync(0xffffffffu, x, d);
        if (lane >= d) x += t;
    }
    if (lane == 31) s_part[wid] = x;
    __syncthreads();
    if (wid == 0) {
        float v = s_part[lane];
        float y = v;
#pragma unroll
        for (int d = 1; d < 32; d <<= 1) {
            float t = __shfl_up_sync(0xffffffffu, y, d);
            if (lane >= d) y += t;
        }
        s_part[lane] = y - v;
    }
    __syncthreads();
    return s_part[wid] + (x - local_total);
}

// exact per-grid-point circular-CDF value (identical arithmetic across all
// call sites -- bit-for-bit, so racy duplicate writes are benign).
__device__ __forceinline__ float eval_ecdf(int j, const float* xs, const float* cw,
                                           const int* offs)
{
    float xn = fmaf((float)j, STEPG, -1.0f);
    float fi = (float)((j >> 13) - 1);         // period constant
    if (j == NG - 1) fi = floorf(xn);          // xn ~ 2.0 endpoint
    float r = xn - fi;
    int b = (int)(r * 8192.0f);
    if (b > NS - 1) b = NS - 1;
    if (b < 0) b = 0;
    int lo = offs[b], hi = offs[b + 1];
    int cnt = lo;
    for (int i = lo; i < hi; i++) cnt += (xs[i] < r) ? 1 : 0;
    int idx = cnt - 1;
    idx = idx < 0 ? 0 : (idx > NS - 2 ? NS - 2 : idx);
    float t = __fdividef(r - xs[idx], xs[idx + 1] - xs[idx]);
    return fi + fmaf(t, cw[idx + 1] - cw[idx], cw[idx]);
}

// full exact lower_bound bisection -- identical probe path to jnp.searchsorted.
__device__ __forceinline__ int full_bisect(const float* ecdf, float y)
{
    int lo = 0, hi = NG;
#pragma unroll
    for (int it = 0; it < 15; it++) {
        int mid = (lo + hi) >> 1;
        bool c = ecdf[mid] < y;
        lo = c ? mid + 1 : lo;
        hi = c ? hi : mid;
    }
    return lo;
}

// value-driven bisection with on-the-fly evaluation; stashes every probed
// value into ecdf[]. The stashed indices cover every probe outside
// [jlo, jhi] made by any query landing inside (covering argument: such a
// probe's fixed-tree node contains both the probe and jlo (or jhi), hence
// lies on the jlo- / jhi-path at that depth).
__device__ __forceinline__ int bisect_eval_stash(float* ecdf, const float* xs,
                                                 const float* cw, const int* offs,
                                                 float y)
{
    int lo = 0, hi = NG;
#pragma unroll
    for (int it = 0; it < 15; it++) {
        int mid = (lo + hi) >> 1;
        float v = eval_ecdf(mid, xs, cw, offs);
        ecdf[mid] = v;
        bool c = v < y;
        lo = c ? mid + 1 : lo;
        hi = c ? hi : mid;
    }
    return lo;
}

// ---------------------------------------------------------------------------
// one embedding pass per block: grid = 1024 = 2 datasets x 512 rows
// fully fused: emb -> per-row distance (2nd finisher) -> final scalar (last)
// ---------------------------------------------------------------------------
__global__ void __launch_bounds__(NTHREADS, 1)
lcot_emb_kernel(const float* __restrict__ x1, const float* __restrict__ w1,
                const float* __restrict__ x2, const float* __restrict__ w2,
                float* __restrict__ out)
{
    extern __shared__ char smem_raw[];
    float* xs   = (float*)smem_raw;            // [NS]
    float* cw   = xs + NS;                     // [NS]
    int*   offs = (int*)(cw + NS);             // [NS+1]
    float* ecdf = (float*)(offs + (NS + 1));   // [NG]

    __shared__ float s_pf[32];
    __shared__ float s_pf2[32];
    __shared__ int   s_pi[32];
    __shared__ float s_alpha;
    __shared__ int   s_jlo, s_jhi;
    __shared__ int   s_second, s_last;

    const int tid = threadIdx.x;
    const int bid = blockIdx.x;
    const int row = bid & (LROWS - 1);
    const int ds  = bid >> 9;
    const size_t base = (size_t)row * NS;
    const float* gx = (ds ? x2 : x1) + base;
    const float* gw = (ds ? w2 : w1) + base;
    float* hout = g_h + (size_t)bid * NS;

    // ---- 1. zero histogram --------------------------------------------------
    for (int i = tid; i <= NS; i += NTHREADS) offs[i] = 0;
    __syncthreads();

    // ---- 2. vectorized load, histogram, alpha partials ----------------------
    float lx[IPT], lw[IPT];
    float pxw = 0.f, pw = 0.f;
    {
        const float4* gx4 = (const float4*)gx;
        const float4* gw4 = (const float4*)gw;
#pragma unroll
        for (int v = 0; v < IPT / 4; v++) {
            float4 X = gx4[tid + v * NTHREADS];
            float4 W = gw4[tid + v * NTHREADS];
            lx[v*4+0] = X.x; lx[v*4+1] = X.y; lx[v*4+2] = X.z; lx[v*4+3] = X.w;
            lw[v*4+0] = W.x; lw[v*4+1] = W.y; lw[v*4+2] = W.z; lw[v*4+3] = W.w;
        }
#pragma unroll
        for (int i = 0; i < IPT; i++) {
            pxw += lx[i] * lw[i]; pw += lw[i];
            int b = (int)(lx[i] * 8192.0f);    // exact order-preserving bucket
            if (b > NS - 1) b = NS - 1;
            atomicAdd(&offs[b + 1], 1);
        }
    }
    {
        int lane = tid & 31, wid = tid >> 5;
        float a = pxw, b = pw;
#pragma unroll
        for (int d = 16; d > 0; d >>= 1) {
            a += __shfl_down_sync(0xffffffffu, a, d);
            b += __shfl_down_sync(0xffffffffu, b, d);
        }
        if (lane == 0) { s_pf[wid] = a; s_pf2[wid] = b; }
        __syncthreads();                       // also fences histogram atomics
        if (tid == 0) {
            float sa = 0.f, sb = 0.f;
#pragma unroll
            for (int k = 0; k < 32; k++) { sa += s_pf[k]; sb += s_pf2[k]; }
            s_alpha = sa / sb - 0.5f;
        }
    }

    // ---- 3. exclusive scan of counts -> bucket offsets ----------------------
    {
        int c[IPT]; int runc = 0;
#pragma unroll
        for (int j = 0; j < IPT; j++) {
            runc += offs[1 + tid * IPT + j];
            c[j] = runc;
        }
        int exc = block_excl_scan_int(runc, tid, s_pi);
#pragma unroll
        for (int j = 0; j < IPT; j++) offs[1 + tid * IPT + j] = exc + c[j];
        __syncthreads();
    }

    // ---- 4. scatter (counting sort); cursors live in ecdf region ------------
    {
        int* cursor = (int*)ecdf;
        for (int b = tid; b < NS; b += NTHREADS) cursor[b] = offs[b];
        __syncthreads();
#pragma unroll
        for (int i = 0; i < IPT; i++) {
            float x = lx[i];
            int b = (int)(x * 8192.0f);
            if (b > NS - 1) b = NS - 1;
            int pos = atomicAdd(&cursor[b], 1);
            xs[pos] = x;
            cw[pos] = lw[i];
        }
        __syncthreads();
    }

    // ---- 5. per-bucket insertion sort (avg occupancy 1) ---------------------
    for (int b = tid; b < NS; b += NTHREADS) {
        int s = offs[b], e = offs[b + 1];
        for (int i = s + 1; i < e; i++) {
            float kx = xs[i], kv = cw[i];
            int j = i - 1;
            while (j >= s && xs[j] > kx) { xs[j+1] = xs[j]; cw[j+1] = cw[j]; j--; }
            xs[j+1] = kx; cw[j+1] = kv;
        }
    }
    __syncthreads();

    // ---- 6. cumsum of sorted weights -> cdf (in place) ----------------------
    {
        float v[IPT]; float runf = 0.f;
#pragma unroll
        for (int j = 0; j < IPT; j++) { runf += cw[tid * IPT + j]; v[j] = runf; }
        float excf = block_excl_scan_float(runf, tid, s_pf);
#pragma unroll
        for (int j = 0; j < IPT; j++) cw[tid * IPT + j] = excf + v[j];
        __syncthreads();
    }

    // ---- 7a. overlap: stashing mini-bisections || speculative raster --------
    const float alpha_r = s_alpha;
    int spec_lo, spec_hi;
    {
        int est = (int)((1.0f - alpha_r) * (24575.0f / 3.0f));
        spec_lo = est - 288;         if (spec_lo < 0) spec_lo = 0;
        spec_hi = est + NS + 576;    if (spec_hi > NG - 1) spec_hi = NG - 1;
        if (tid == 0)
            s_jlo = bisect_eval_stash(ecdf, xs, cw, offs, 0.0f - alpha_r);
        else if (tid == 32)
            s_jhi = bisect_eval_stash(ecdf, xs, cw, offs,
                                      (float)(NREF - 1) * INVN - alpha_r);
        else if (tid >= 64) {
            for (int j = spec_lo + (tid - 64); j <= spec_hi; j += NTHREADS - 64)
                ecdf[j] = eval_ecdf(j, xs, cw, offs);
        }
    }
    __syncthreads();

    // ---- 7b. gap fill: [jlo-1, jhi] minus the speculative window ------------
    {
        int jstart = s_jlo - 1; if (jstart < 0) jstart = 0;
        int jend   = s_jhi;     if (jend > NG - 1) jend = NG - 1;
        for (int j = jstart + tid; j <= jend; j += NTHREADS)
            if (j < spec_lo || j > spec_hi)
                ecdf[j] = eval_ecdf(j, xs, cw, offs);
    }
    __syncthreads();

    // ---- 8. invert CDF: bracketed exact inversion ---------------------------
    // Fence landings bracket the 7 intermediate ones (landings monotone in y);
    // bracket avoiding {8192, 16384, NG-1} => restricted bisection lands
    // identically; else exact full-bisect fallback. tid 1023's upper fence is
    // s_jhi (= exact landing of y(NREF-1)); y(NREF) is never probed.
    const int k0 = tid * KPT;
    {
        float y0 = (float)k0 * INVN - alpha_r;
        int posA = full_bisect(ecdf, y0);
        int posB = __shfl_down_sync(0xffffffffu, posA, 1);
        if ((tid & 31) == 31) {
            posB = (tid == NTHREADS - 1)
                 ? s_jhi
                 : full_bisect(ecdf, (float)(k0 + KPT) * INVN - alpha_r);
        }

        int pos[KPT];
        pos[0] = posA;
        bool unsafe = (8192  >= posA && 8192  <= posB) ||
                      (16384 >= posA && 16384 <= posB) ||
                      (NG - 1 >= posA && NG - 1 <= posB);
        if (!unsafe) {
            int hi_q[KPT];
#pragma unroll
            for (int q = 1; q < KPT; q++) { pos[q] = posA; hi_q[q] = posB; }
            int w = posB - posA;
            while (w > 0) {
#pragma unroll
                for (int q = 1; q < KPT; q++) {
                    if (pos[q] < hi_q[q]) {
                        int mid = (pos[q] + hi_q[q]) >> 1;
                        bool c = ecdf[mid] < ((float)(k0 + q) * INVN - alpha_r);
                        pos[q]  = c ? mid + 1 : pos[q];
                        hi_q[q] = c ? hi_q[q] : mid;
                    }
                }
                w >>= 1;
            }
        } else {
#pragma unroll
            for (int q = 1; q < KPT; q++)
                pos[q] = full_bisect(ecdf, (float)(k0 + q) * INVN - alpha_r);
        }

        float4 outv[KPT / 4];
        float* outf = (float*)outv;
#pragma unroll
        for (int q = 0; q < KPT; q++) {
            int k = k0 + q;
            float xk = (float)k * INVN;
            float yq = xk - alpha_r;
            int idx = pos[q] - 1;
            idx = idx < 0 ? 0 : (idx > NG - 2 ? NG - 2 : idx);
            float e0 = ecdf[idx], e1 = ecdf[idx + 1];
            float xn0 = fmaf((float)idx,       STEPG, -1.0f);
            float xn1 = fmaf((float)(idx + 1), STEPG, -1.0f);
            float t = __fdividef(yq - e0, e1 - e0);
            outf[q] = fmaf(t, xn1 - xn0, xn0) - xk;
        }
        float4* hv = (float4*)(hout + k0);
        hv[0] = outv[0];
        hv[1] = outv[1];
    }

    // ---- 9. fused distance (2nd finisher per row) ---------------------------
    __threadfence();
    __syncthreads();                           // all h writes of block done
    if (tid == 0) {
        int old = atomicAdd(&g_done[row], 1);
        s_second = (old == 1);
        if (old == 1) g_done[row] = 0;         // self-reset for graph replays
        s_last = 0;
    }
    __syncthreads();
    if (s_second) {
        __threadfence();                       // acquire partner's h writes
        const float* hA = g_h + (size_t)row * NS;
        const float* hB = g_h + (size_t)(LROWS + row) * NS;
        float4 a0 = *(const float4*)(hA + k0);
        float4 a1 = *(const float4*)(hA + k0 + 4);
        float4 b0 = *(const float4*)(hB + k0);
        float4 b1 = *(const float4*)(hB + k0 + 4);
        float acc = 0.f;
        {
            const float* pa = (const float*)&a0;
            const float* pb = (const float*)&b0;
#pragma unroll
            for (int i = 0; i < 4; i++) {
                float d = fabsf(pb[i] - pa[i]);
                float m = fminf(d, 1.0f - d);
                acc = fmaf(m, m, acc);
            }
            pa = (const float*)&a1; pb = (const float*)&b1;
#pragma unroll
            for (int i = 0; i < 4; i++) {
                float d = fabsf(pb[i] - pa[i]);
                float m = fminf(d, 1.0f - d);
                acc = fmaf(m, m, acc);
            }
        }
        int lane = tid & 31, wid = tid >> 5;
#pragma unroll
        for (int d = 16; d > 0; d >>= 1)
            acc += __shfl_down_sync(0xffffffffu, acc, d);
        if (lane == 0) s_pf[wid] = acc;
        __syncthreads();
        if (tid == 0) {
            float s = 0.f;
#pragma unroll
            for (int k = 0; k < 32; k++) s += s_pf[k];
            g_rowsum[row] = s;
            __threadfence();                   // release rowsum
            int old2 = atomicAdd(&g_nrows, 1);
            s_last = (old2 == LROWS - 1);
            if (s_last) g_nrows = 0;           // self-reset for graph replays
        }
        __syncthreads();

        // ---- 10. fused finalize (the very last finisher block) --------------
        if (s_last) {
            __threadfence();                   // acquire all rowsums
            float* red = (float*)smem_raw;     // reuse smem (xs region)
            if (tid < LROWS) red[tid] = g_rowsum[tid];
            __syncthreads();
            for (int s = LROWS / 2; s > 0; s >>= 1) {
                if (tid < s) red[tid] += red[tid + s];
                __syncthreads();
            }
            if (tid == 0) out[0] = sqrtf(red[0] / (float)LROWS);
        }
    }
}

extern "C" void kernel_launch(void* const* d_in, const int* in_sizes, int n_in,
                              void* d_out, int out_size)
{
    const float* x1 = (const float*)d_in[0];
    const float* w1 = (const float*)d_in[1];
    const float* x2 = (const float*)d_in[2];
    const float* w2 = (const float*)d_in[3];
    float* out = (float*)d_out;

    size_t dyn = (size_t)(2 * NS) * sizeof(float)
               + (size_t)(NS + 1) * sizeof(int)
               + (size_t)NG * sizeof(float);   // 196612 B

    cudaFuncSetAttribute(lcot_emb_kernel,
                         cudaFuncAttributeMaxDynamicSharedMemorySize, (int)dyn);

    lcot_emb_kernel<<<2 * LROWS, NTHREADS, dyn>>>(x1, w1, x2, w2, out);
}

// round 13
// speedup vs baseline: 1.3331x; 1.0174x over previous
#include <cuda_runtime.h>
#include <math.h>

#define LROWS    512
#define NS       8192            // samples per row
#define NREF     8192            // reference grid points
#define NG       (3*NREF)        // 24576 circular-CDF grid points
#define NTHREADS 1024
#define IPT      (NS/NTHREADS)   // 8 items per thread
#define KPT      (NREF/NTHREADS) // 8 inversion queries per thread (consecutive)

#define STEPG  (3.0f/24575.0f)
#define INVN   (1.0f/8192.0f)

__device__ float g_rowsum[LROWS];
__device__ int   g_done[LROWS];                 // zero-init; self-resetting
__device__ int   g_nrows;                       // zero-init; self-resetting
__device__ float g_h[(size_t)2 * LROWS * NS];   // h1 then h2, 32 MB scratch

// ---------------------------------------------------------------------------
// block-wide exclusive scans (warp shuffle + 32-entry partials)
// ---------------------------------------------------------------------------
__device__ __forceinline__ int block_excl_scan_int(int local_total, int tid, int* s_part)
{
    __syncthreads();
    int lane = tid & 31, wid = tid >> 5;
    int x = local_total;
#pragma unroll
    for (int d = 1; d < 32; d <<= 1) {
        int t = __shfl_up_sync(0xffffffffu, x, d);
        if (lane >= d) x += t;
    }
    if (lane == 31) s_part[wid] = x;
    __syncthreads();
    if (wid == 0) {
        int v = s_part[lane];
        int y = v;
#pragma unroll
        for (int d = 1; d < 32; d <<= 1) {
            int t = __shfl_up_sync(0xffffffffu, y, d);
            if (lane >= d) y += t;
        }
        s_part[lane] = y - v;                  // exclusive warp offsets
    }
    __syncthreads();
    return s_part[wid] + (x - local_total);
}

__device__ __forceinline__ float block_excl_scan_float(float local_total, int tid, float* s_part)
{
    __syncthreads();
    int lane = tid & 31, wid = tid >> 5;
    float x = local_total;
#pragma unroll
    for (int d = 1; d < 32; d <<= 1) {
        float t = __shfl_up_sync(0xffffffffu, x, d);
        if (lane >= d) x += t;
    }
    if (lane == 31) s_part[wid] = x;
    __syncthreads();
    if (wid == 0) {
        float v = s_part[lane];
        float y = v;
#pragma unroll
        for (int d = 1; d < 32; d <<= 1) {
            float t = __shfl_up_sync(0xffffffffu, y, d);
            if (lane >= d) y += t;
        }
        s_part[lane] = y - v;
    }
    __syncthreads();
    return s_part[wid] + (x - local_total);
}

// exact per-grid-point circular-CDF value (identical arithmetic across all
// call sites -- bit-for-bit, so racy duplicate writes are benign).
__device__ __forceinline__ float eval_ecdf(int j, const float* xs, const float* cw,
                                           const int* offs)
{
    float xn = fmaf((float)j, STEPG, -1.0f);
    float fi = (float)((j >> 13) - 1);         // period constant
    if (j == NG - 1) fi = floorf(xn);          // xn ~ 2.0 endpoint
    float r = xn - fi;
    int b = (int)(r * 8192.0f);
    if (b > NS - 1) b = NS - 1;
    if (b < 0) b = 0;
    int lo = offs[b], hi = offs[b + 1];
    int cnt = lo;
    for (int i = lo; i < hi; i++) cnt += (xs[i] < r) ? 1 : 0;
    int idx = cnt - 1;
    idx = idx < 0 ? 0 : (idx > NS - 2 ? NS - 2 : idx);
    float t = __fdividef(r - xs[idx], xs[idx + 1] - xs[idx]);
    return fi + fmaf(t, cw[idx + 1] - cw[idx], cw[idx]);
}

// full exact lower_bound bisection -- identical probe path to jnp.searchsorted.
__device__ __forceinline__ int full_bisect(const float* ecdf, float y)
{
    int lo = 0, hi = NG;
#pragma unroll
    for (int it = 0; it < 15; it++) {
        int mid = (lo + hi) >> 1;
        bool c = ecdf[mid] < y;
        lo = c ? mid + 1 : lo;
        hi = c ? hi : mid;
    }
    return lo;
}

// value-driven bisection with on-the-fly evaluation; stashes every probed
// value into ecdf[]. The stashed indices cover every probe outside
// [jlo, jhi] made by any query landing inside (covering argument: such a
// probe's fixed-tree node contains both the probe and jlo (or jhi), hence
// lies on the jlo- / jhi-path at that depth).
__device__ __forceinline__ int bisect_eval_stash(float* ecdf, const float* xs,
                                                 const float* cw, const int* offs,
                                                 float y)
{
    int lo = 0, hi = NG;
#pragma unroll
    for (int it = 0; it < 15; it++) {
        int mid = (lo + hi) >> 1;
        float v = eval_ecdf(mid, xs, cw, offs);
        ecdf[mid] = v;
        bool c = v < y;
        lo = c ? mid + 1 : lo;
        hi = c ? hi : mid;
    }
    return lo;
}

// ---------------------------------------------------------------------------
// one embedding pass per block: grid = 1024 = 2 datasets x 512 rows
// fully fused: emb -> per-row distance (2nd finisher) -> final scalar (last)
// ---------------------------------------------------------------------------
__global__ void __launch_bounds__(NTHREADS, 1)
lcot_emb_kernel(const float* __restrict__ x1, const float* __restrict__ w1,
                const float* __restrict__ x2, const float* __restrict__ w2,
                float* __restrict__ out)
{
    extern __shared__ char smem_raw[];
    float* xs   = (float*)smem_raw;            // [NS]
    float* cw   = xs + NS;                     // [NS]
    int*   offs = (int*)(cw + NS);             // [NS+1]
    float* ecdf = (float*)(offs + (NS + 1));   // [NG]

    __shared__ float s_pf[32];
    __shared__ float s_pf2[32];
    __shared__ int   s_pi[32];
    __shared__ float s_alpha;
    __shared__ int   s_jlo, s_jhi;
    __shared__ int   s_second, s_last;

    const int tid = threadIdx.x;
    const int bid = blockIdx.x;
    const int row = bid & (LROWS - 1);
    const int ds  = bid >> 9;
    const size_t base = (size_t)row * NS;
    const float* gx = (ds ? x2 : x1) + base;
    const float* gw = (ds ? w2 : w1) + base;
    float* hout = g_h + (size_t)bid * NS;

    // ---- 1. zero histogram --------------------------------------------------
    for (int i = tid; i <= NS; i += NTHREADS) offs[i] = 0;
    __syncthreads();

    // ---- 2. vectorized load, histogram, alpha partials ----------------------
    float lx[IPT], lw[IPT];
    float pxw = 0.f, pw = 0.f;
    {
        const float4* gx4 = (const float4*)gx;
        const float4* gw4 = (const float4*)gw;
#pragma unroll
        for (int v = 0; v < IPT / 4; v++) {
            float4 X = gx4[tid + v * NTHREADS];
            float4 W = gw4[tid + v * NTHREADS];
            lx[v*4+0] = X.x; lx[v*4+1] = X.y; lx[v*4+2] = X.z; lx[v*4+3] = X.w;
            lw[v*4+0] = W.x; lw[v*4+1] = W.y; lw[v*4+2] = W.z; lw[v*4+3] = W.w;
        }
#pragma unroll
        for (int i = 0; i < IPT; i++) {
            pxw += lx[i] * lw[i]; pw += lw[i];
            int b = (int)(lx[i] * 8192.0f);    // exact order-preserving bucket
            if (b > NS - 1) b = NS - 1;
            atomicAdd(&offs[b + 1], 1);
        }
    }
    {
        int lane = tid & 31, wid = tid >> 5;
        float a = pxw, b = pw;
#pragma unroll
        for (int d = 16; d > 0; d >>= 1) {
            a += __shfl_down_sync(0xffffffffu, a, d);
            b += __shfl_down_sync(0xffffffffu, b, d);
        }
        if (lane == 0) { s_pf[wid] = a; s_pf2[wid] = b; }
        __syncthreads();                       // also fences histogram atomics
        if (tid == 0) {
            float sa = 0.f, sb = 0.f;
#pragma unroll
            for (int k = 0; k < 32; k++) { sa += s_pf[k]; sb += s_pf2[k]; }
            s_alpha = sa / sb - 0.5f;
        }
    }

    // ---- 3. exclusive scan of counts -> bucket offsets ----------------------
    {
        int c[IPT]; int runc = 0;
#pragma unroll
        for (int j = 0; j < IPT; j++) {
            runc += offs[1 + tid * IPT + j];
            c[j] = runc;
        }
        int exc = block_excl_scan_int(runc, tid, s_pi);
#pragma unroll
        for (int j = 0; j < IPT; j++) offs[1 + tid * IPT + j] = exc + c[j];
        __syncthreads();
    }

    // ---- 4. scatter (counting sort); cursors live in ecdf region ------------
    {
        int* cursor = (int*)ecdf;
        for (int b = tid; b < NS; b += NTHREADS) cursor[b] = offs[b];
        __syncthreads();
#pragma unroll
        for (int i = 0; i < IPT; i++) {
            float x = lx[i];
            int b = (int)(x * 8192.0f);
            if (b > NS - 1) b = NS - 1;
            int pos = atomicAdd(&cursor[b], 1);
            xs[pos] = x;
            cw[pos] = lw[i];
        }
        __syncthreads();
    }

    // ---- 5. per-bucket insertion sort (avg occupancy 1) ---------------------
    for (int b = tid; b < NS; b += NTHREADS) {
        int s = offs[b], e = offs[b + 1];
        for (int i = s + 1; i < e; i++) {
            float kx = xs[i], kv = cw[i];
            int j = i - 1;
            while (j >= s && xs[j] > kx) { xs[j+1] = xs[j]; cw[j+1] = cw[j]; j--; }
            xs[j+1] = kx; cw[j+1] = kv;
        }
    }
    __syncthreads();

    // ---- 6. cumsum of sorted weights -> cdf (in place) ----------------------
    {
        float v[IPT]; float runf = 0.f;
#pragma unroll
        for (int j = 0; j < IPT; j++) { runf += cw[tid * IPT + j]; v[j] = runf; }
        float excf = block_excl_scan_float(runf, tid, s_pf);
#pragma unroll
        for (int j = 0; j < IPT; j++) cw[tid * IPT + j] = excf + v[j];
        __syncthreads();
    }

    // ---- 7a. overlap: stashing mini-bisections || speculative raster --------
    const float alpha_r = s_alpha;
    int spec_lo, spec_hi;
    {
        int est = (int)((1.0f - alpha_r) * (24575.0f / 3.0f));
        spec_lo = est - 288;         if (spec_lo < 0) spec_lo = 0;
        spec_hi = est + NS + 576;    if (spec_hi > NG - 1) spec_hi = NG - 1;
        if (tid == 0)
            s_jlo = bisect_eval_stash(ecdf, xs, cw, offs, 0.0f - alpha_r);
        else if (tid == 32)
            s_jhi = bisect_eval_stash(ecdf, xs, cw, offs,
                                      (float)(NREF - 1) * INVN - alpha_r);
        else if (tid >= 64) {
            for (int j = spec_lo + (tid - 64); j <= spec_hi; j += NTHREADS - 64)
                ecdf[j] = eval_ecdf(j, xs, cw, offs);
        }
    }
    __syncthreads();

    // ---- 7b. gap fill: only the (normally empty) ranges the speculative
    // window missed: [jstart, spec_lo) and (spec_hi, jend] ---------------------
    {
        int jstart = s_jlo - 1; if (jstart < 0) jstart = 0;
        int jend   = s_jhi;     if (jend > NG - 1) jend = NG - 1;
        for (int j = jstart + tid; j < spec_lo; j += NTHREADS)
            ecdf[j] = eval_ecdf(j, xs, cw, offs);
        for (int j = spec_hi + 1 + tid; j <= jend; j += NTHREADS)
            ecdf[j] = eval_ecdf(j, xs, cw, offs);
    }
    __syncthreads();

    // ---- 8. invert CDF: bracketed exact inversion ---------------------------
    // Fence landings bracket the 7 intermediate ones (landings monotone in y).
    // Safe bracket (no drop index in [posA, posB]) => region monotone =>
    // landing = posA + #{i in [posA,posB): ecdf[i] < y} (count sweep, one LDS
    // per bracket element shared by all 7 queries). Wide or unsafe brackets
    // fall back to bisection -- all paths land identically.
    const int k0 = tid * KPT;
    {
        float y0 = (float)k0 * INVN - alpha_r;
        int posA = full_bisect(ecdf, y0);
        int posB = __shfl_down_sync(0xffffffffu, posA, 1);
        if ((tid & 31) == 31) {
            posB = (tid == NTHREADS - 1)
                 ? s_jhi
                 : full_bisect(ecdf, (float)(k0 + KPT) * INVN - alpha_r);
        }

        float yq[KPT];
#pragma unroll
        for (int q = 1; q < KPT; q++)
            yq[q] = (float)(k0 + q) * INVN - alpha_r;

        int pos[KPT];
        pos[0] = posA;
        int w = posB - posA;
        bool unsafe = (8192  >= posA && 8192  <= posB) ||
                      (16384 >= posA && 16384 <= posB) ||
                      (NG - 1 >= posA && NG - 1 <= posB);
        if (!unsafe && w <= 64) {
            // count sweep: sequential LDS, each value serves all 7 queries
            int cnt[KPT];
#pragma unroll
            for (int q = 1; q < KPT; q++) cnt[q] = 0;
            for (int i = posA; i < posB; i++) {
                float e = ecdf[i];
#pragma unroll
                for (int q = 1; q < KPT; q++) cnt[q] += (e < yq[q]) ? 1 : 0;
            }
#pragma unroll
            for (int q = 1; q < KPT; q++) pos[q] = posA + cnt[q];
        } else if (!unsafe) {
            // wide monotone bracket: restricted bisection (identical landing)
            int hi_q[KPT];
#pragma unroll
            for (int q = 1; q < KPT; q++) { pos[q] = posA; hi_q[q] = posB; }
            while (w > 0) {
#pragma unroll
                for (int q = 1; q < KPT; q++) {
                    if (pos[q] < hi_q[q]) {
                        int mid = (pos[q] + hi_q[q]) >> 1;
                        bool c = ecdf[mid] < yq[q];
                        pos[q]  = c ? mid + 1 : pos[q];
                        hi_q[q] = c ? hi_q[q] : mid;
                    }
                }
                w >>= 1;
            }
        } else {
            // bracket touches a possible non-monotone index: exact fallback
#pragma unroll
            for (int q = 1; q < KPT; q++)
                pos[q] = full_bisect(ecdf, yq[q]);
        }

        float4 outv[KPT / 4];
        float* outf = (float*)outv;
#pragma unroll
        for (int q = 0; q < KPT; q++) {
            int k = k0 + q;
            float xk = (float)k * INVN;
            float yv = xk - alpha_r;
            int idx = pos[q] - 1;
            idx = idx < 0 ? 0 : (idx > NG - 2 ? NG - 2 : idx);
            float e0 = ecdf[idx], e1 = ecdf[idx + 1];
            float xn0 = fmaf((float)idx,       STEPG, -1.0f);
            float xn1 = fmaf((float)(idx + 1), STEPG, -1.0f);
            float t = __fdividef(yv - e0, e1 - e0);
            outf[q] = fmaf(t, xn1 - xn0, xn0) - xk;
        }
        float4* hv = (float4*)(hout + k0);
        hv[0] = outv[0];
        hv[1] = outv[1];
    }

    // ---- 9. fused distance (2nd finisher per row) ---------------------------
    __threadfence();
    __syncthreads();                           // all h writes of block done
    if (tid == 0) {
        int old = atomicAdd(&g_done[row], 1);
        s_second = (old == 1);
        if (old == 1) g_done[row] = 0;         // self-reset for graph replays
        s_last = 0;
    }
    __syncthreads();
    if (s_second) {
        __threadfence();                       // acquire partner's h writes
        const float* hA = g_h + (size_t)row * NS;
        const float* hB = g_h + (size_t)(LROWS + row) * NS;
        float4 a0 = *(const float4*)(hA + k0);
        float4 a1 = *(const float4*)(hA + k0 + 4);
        float4 b0 = *(const float4*)(hB + k0);
        float4 b1 = *(const float4*)(hB + k0 + 4);
        float acc = 0.f;
        {
            const float* pa = (const float*)&a0;
            const float* pb = (const float*)&b0;
#pragma unroll
            for (int i = 0; i < 4; i++) {
                float d = fabsf(pb[i] - pa[i]);
                float m = fminf(d, 1.0f - d);
                acc = fmaf(m, m, acc);
            }
            pa = (const float*)&a1; pb = (const float*)&b1;
#pragma unroll
            for (int i = 0; i < 4; i++) {
                float d = fabsf(pb[i] - pa[i]);
                float m = fminf(d, 1.0f - d);
                acc = fmaf(m, m, acc);
            }
        }
        int lane = tid & 31, wid = tid >> 5;
#pragma unroll
        for (int d = 16; d > 0; d >>= 1)
            acc += __shfl_down_sync(0xffffffffu, acc, d);
        if (lane == 0) s_pf[wid] = acc;
        __syncthreads();
        if (tid == 0) {
            float s = 0.f;
#pragma unroll
            for (int k = 0; k < 32; k++) s += s_pf[k];
            g_rowsum[row] = s;
            __threadfence();                   // release rowsum
            int old2 = atomicAdd(&g_nrows, 1);
            s_last = (old2 == LROWS - 1);
            if (s_last) g_nrows = 0;           // self-reset for graph replays
        }
        __syncthreads();

        // ---- 10. fused finalize (the very last finisher block) --------------
        if (s_last) {
            __threadfence();                   // acquire all rowsums
            float* red = (float*)smem_raw;     // reuse smem (xs region)
            if (tid < LROWS) red[tid] = g_rowsum[tid];
            __syncthreads();
            for (int s = LROWS / 2; s > 0; s >>= 1) {
                if (tid < s) red[tid] += red[tid + s];
                __syncthreads();
            }
            if (tid == 0) out[0] = sqrtf(red[0] / (float)LROWS);
        }
    }
}

extern "C" void kernel_launch(void* const* d_in, const int* in_sizes, int n_in,
                              void* d_out, int out_size)
{
    const float* x1 = (const float*)d_in[0];
    const float* w1 = (const float*)d_in[1];
    const float* x2 = (const float*)d_in[2];
    const float* w2 = (const float*)d_in[3];
    float* out = (float*)d_out;

    size_t dyn = (size_t)(2 * NS) * sizeof(float)
               + (size_t)(NS + 1) * sizeof(int)
               + (size_t)NG * sizeof(float);   // 196612 B

    cudaFuncSetAttribute(lcot_emb_kernel,
                         cudaFuncAttributeMaxDynamicSharedMemorySize, (int)dyn);

    lcot_emb_kernel<<<2 * LROWS, NTHREADS, dyn>>>(x1, w1, x2, w2, out);
}